// round 10
// baseline (speedup 1.0000x reference)
#include <cuda_runtime.h>
#include <cuda_bf16.h>
#include <math.h>
#include <stdint.h>

// Problem constants
#define T_STEPS 128
#define BATCH   256
#define V_DIM   256
#define N_DIM   1024
#define TB      (T_STEPS * BATCH)          // 32768
#define SLAB    (BATCH * N_DIM)            // 262144 floats per time slab
#define NSPLIT  8                          // split-K factor for recurrent GEMM

// Scratch (device globals: no allocations allowed)
__device__ float g_seq[(size_t)T_STEPS * SLAB];   // 128 MB: xw pre-activations, then h_t in place
__device__ float g_part[(size_t)NSPLIT * SLAB];   // 8 MB: split-K partials
__device__ float g_logits[(size_t)TB * V_DIM];    // 33.5 MB
__device__ float g_rowloss[TB];
__device__ unsigned g_tile_cnt[64];               // zero-init; wraps back to 0 each step

__device__ __forceinline__ uint32_t f2tf32(float x) {
    uint32_t r;
    asm("cvt.rna.tf32.f32 %0, %1;" : "=r"(r) : "f"(x));
    return r;
}

__device__ __forceinline__ void mma_tf32(float c[4], uint32_t a0, uint32_t a1,
                                         uint32_t a2, uint32_t a3,
                                         uint32_t b0, uint32_t b1) {
    asm volatile(
        "mma.sync.aligned.m16n8k8.row.col.f32.tf32.tf32.f32 "
        "{%0,%1,%2,%3}, {%4,%5,%6,%7}, {%8,%9}, {%0,%1,%2,%3};"
        : "+f"(c[0]), "+f"(c[1]), "+f"(c[2]), "+f"(c[3])
        : "r"(a0), "r"(a1), "r"(a2), "r"(a3), "r"(b0), "r"(b1));
}

#define AS_STRIDE 20   // words; conflict-free A-fragment LDS (BK=16)
#define BS_STRIDE 72   // words; conflict-free B-fragment LDS

// ---------------------------------------------------------------------------
// Shared GEMM core: computes this block's 64x64 tf32 partial into acc[2][4][4].
// Block tile 64x64, 128 threads = 4 warps (2x2), each warp 32x32, BK=16.
// ---------------------------------------------------------------------------
__device__ __forceinline__ void gemm_core(
    const float* __restrict__ A, const float* __restrict__ B,
    int lda, int ldb, int row0, int col0, int k0, int kChunk,
    uint32_t* As, uint32_t* Bs, float acc[2][4][4])
{
    const int tid  = threadIdx.x;
    const int warp = tid >> 5;
    const int lane = tid & 31;
    const int gid  = lane >> 2;
    const int tg   = lane & 3;
    const int wm = (warp >> 1) * 32;
    const int wn = (warp & 1) * 32;

    const int a_r0 = tid >> 2;
    const int a_c4 = (tid & 3) * 4;
    const int b_r0 = tid >> 4;
    const int b_c4 = (tid & 15) * 4;

    for (int kt = 0; kt < kChunk; kt += 16) {
#pragma unroll
        for (int h = 0; h < 2; h++) {
            int ar = a_r0 + h * 32;
            float4 av = *(const float4*)(A + (size_t)(row0 + ar) * lda + (k0 + kt + a_c4));
            uint32_t* dst = &As[ar * AS_STRIDE + a_c4];
            dst[0] = f2tf32(av.x); dst[1] = f2tf32(av.y);
            dst[2] = f2tf32(av.z); dst[3] = f2tf32(av.w);
        }
#pragma unroll
        for (int h = 0; h < 2; h++) {
            int br = b_r0 + h * 8;
            float4 bv = *(const float4*)(B + (size_t)(k0 + kt + br) * ldb + (col0 + b_c4));
            uint32_t* dst = &Bs[br * BS_STRIDE + b_c4];
            dst[0] = f2tf32(bv.x); dst[1] = f2tf32(bv.y);
            dst[2] = f2tf32(bv.z); dst[3] = f2tf32(bv.w);
        }
        __syncthreads();

#pragma unroll
        for (int ks = 0; ks < 2; ks++) {
            const int kk = ks * 8;
            uint32_t afrag[2][4];
#pragma unroll
            for (int mi = 0; mi < 2; mi++) {
                int r = wm + mi * 16 + gid;
                afrag[mi][0] = As[(r    ) * AS_STRIDE + kk + tg    ];
                afrag[mi][1] = As[(r + 8) * AS_STRIDE + kk + tg    ];
                afrag[mi][2] = As[(r    ) * AS_STRIDE + kk + tg + 4];
                afrag[mi][3] = As[(r + 8) * AS_STRIDE + kk + tg + 4];
            }
#pragma unroll
            for (int ni = 0; ni < 4; ni++) {
                int c = wn + ni * 8 + gid;
                uint32_t b0 = Bs[(kk + tg    ) * BS_STRIDE + c];
                uint32_t b1 = Bs[(kk + tg + 4) * BS_STRIDE + c];
#pragma unroll
                for (int mi = 0; mi < 2; mi++)
                    mma_tf32(acc[mi][ni], afrag[mi][0], afrag[mi][1],
                             afrag[mi][2], afrag[mi][3], b0, b1);
            }
        }
        __syncthreads();
    }
}

// ---------------------------------------------------------------------------
// Full GEMM with bias epilogue: C = A@B + bias (used for xw and logits).
// ---------------------------------------------------------------------------
__global__ void __launch_bounds__(128)
mma_gemm(const float* __restrict__ A, const float* __restrict__ B,
         float* __restrict__ C, const float* __restrict__ bias,
         int lda, int ldb, int ldc, int K)
{
    __shared__ uint32_t As[64 * AS_STRIDE];
    __shared__ uint32_t Bs[16 * BS_STRIDE];

    const int tid  = threadIdx.x;
    const int warp = tid >> 5;
    const int lane = tid & 31;
    const int gid  = lane >> 2;
    const int tg   = lane & 3;
    const int wm = (warp >> 1) * 32;
    const int wn = (warp & 1) * 32;
    const int row0 = blockIdx.y * 64;
    const int col0 = blockIdx.x * 64;

    float acc[2][4][4] = {};
    gemm_core(A, B, lda, ldb, row0, col0, 0, K, As, Bs, acc);

#pragma unroll
    for (int mi = 0; mi < 2; mi++) {
        int r0 = row0 + wm + mi * 16 + gid;
#pragma unroll
        for (int ni = 0; ni < 4; ni++) {
            int c = col0 + wn + ni * 8 + tg * 2;
            float b0 = bias[c], b1 = bias[c + 1];
            float2 v0 = make_float2(acc[mi][ni][0] + b0, acc[mi][ni][1] + b1);
            float2 v1 = make_float2(acc[mi][ni][2] + b0, acc[mi][ni][3] + b1);
            *(float2*)(C + (size_t)r0 * ldc + c)       = v0;
            *(float2*)(C + (size_t)(r0 + 8) * ldc + c) = v1;
        }
    }
}

// ---------------------------------------------------------------------------
// One recurrence step, fused: grid (16, 4, NSPLIT).
// Each z-block computes a 64x64 partial of h_{t-1} @ Wh over its k-chunk and
// stores it. The LAST z-block to finish (per tile) sums all partials in fixed
// z order (its own from registers), adds pre, applies tanh, writes h_t.
// Deterministic: summation order is independent of arrival order.
// ---------------------------------------------------------------------------
__global__ void __launch_bounds__(128)
rnn_step(const float* __restrict__ hp, const float* __restrict__ wh,
         float* __restrict__ part, float* __restrict__ cur)
{
    __shared__ uint32_t As[64 * AS_STRIDE];
    __shared__ uint32_t Bs[16 * BS_STRIDE];
    __shared__ unsigned s_last;

    const int tid  = threadIdx.x;
    const int warp = tid >> 5;
    const int lane = tid & 31;
    const int gid  = lane >> 2;
    const int tg   = lane & 3;
    const int wm = (warp >> 1) * 32;
    const int wn = (warp & 1) * 32;
    const int row0 = blockIdx.y * 64;
    const int col0 = blockIdx.x * 64;
    const int z    = blockIdx.z;
    const int kChunk = N_DIM / NSPLIT;   // 128

    float acc[2][4][4] = {};
    gemm_core(hp, wh, N_DIM, N_DIM, row0, col0, z * kChunk, kChunk, As, Bs, acc);

    // store this block's partial
    float* P = part + (size_t)z * SLAB;
#pragma unroll
    for (int mi = 0; mi < 2; mi++) {
        int r0 = row0 + wm + mi * 16 + gid;
#pragma unroll
        for (int ni = 0; ni < 4; ni++) {
            int c = col0 + wn + ni * 8 + tg * 2;
            *(float2*)(P + (size_t)r0 * N_DIM + c)       = make_float2(acc[mi][ni][0], acc[mi][ni][1]);
            *(float2*)(P + (size_t)(r0 + 8) * N_DIM + c) = make_float2(acc[mi][ni][2], acc[mi][ni][3]);
        }
    }

    // last-block election (threadfence reduction pattern)
    __threadfence();
    __syncthreads();
    if (tid == 0) {
        unsigned tileId = blockIdx.y * 16 + blockIdx.x;
        unsigned ticket = atomicInc(&g_tile_cnt[tileId], NSPLIT - 1); // wraps to 0
        s_last = (ticket == NSPLIT - 1);
    }
    __syncthreads();
    if (!s_last) return;

    // last block: h = tanh(pre + sum_z partial_z), fixed z order
#pragma unroll
    for (int mi = 0; mi < 2; mi++) {
        int r0 = row0 + wm + mi * 16 + gid;
#pragma unroll
        for (int ni = 0; ni < 4; ni++) {
            int c = col0 + wn + ni * 8 + tg * 2;
            size_t o0 = (size_t)r0 * N_DIM + c;
            size_t o1 = (size_t)(r0 + 8) * N_DIM + c;
            float2 s0 = *(float2*)(cur + o0);   // pre-activation
            float2 s1 = *(float2*)(cur + o1);
#pragma unroll
            for (int zz = 0; zz < NSPLIT; zz++) {
                if (zz == z) {
                    s0.x += acc[mi][ni][0]; s0.y += acc[mi][ni][1];
                    s1.x += acc[mi][ni][2]; s1.y += acc[mi][ni][3];
                } else {
                    const float* Q = part + (size_t)zz * SLAB;
                    float2 p0 = *(const float2*)(Q + o0);
                    float2 p1 = *(const float2*)(Q + o1);
                    s0.x += p0.x; s0.y += p0.y;
                    s1.x += p1.x; s1.y += p1.y;
                }
            }
            s0.x = tanhf(s0.x); s0.y = tanhf(s0.y);
            s1.x = tanhf(s1.x); s1.y = tanhf(s1.y);
            *(float2*)(cur + o0) = s0;
            *(float2*)(cur + o1) = s1;
        }
    }
}

// h_0 = tanh(xw_0)  — elementwise over one slab (float4 per thread)
__global__ void tanh_slab(float* __restrict__ x)
{
    size_t i = ((size_t)blockIdx.x * blockDim.x + threadIdx.x) * 4;
    float4 v = *(float4*)(x + i);
    v.x = tanhf(v.x); v.y = tanhf(v.y); v.z = tanhf(v.z); v.w = tanhf(v.w);
    *(float4*)(x + i) = v;
}

// Per-row soft-label cross-entropy: one WARP per row, shuffle reductions only.
// rowloss = (max + log(sum exp(logit-max))) * sum(lab) - sum(lab*logit)
__global__ void __launch_bounds__(256)
loss_rows(const float* __restrict__ logits,
          const float* __restrict__ labels,
          float* __restrict__ rowloss)
{
    const int row  = (blockIdx.x * blockDim.x + threadIdx.x) >> 5;
    const int lane = threadIdx.x & 31;

    size_t base = (size_t)row * V_DIM + lane * 8;
    float4 l0 = *(const float4*)(logits + base);
    float4 l1 = *(const float4*)(logits + base + 4);
    float4 a0 = *(const float4*)(labels + base);
    float4 a1 = *(const float4*)(labels + base + 4);

    float mx = fmaxf(fmaxf(fmaxf(l0.x, l0.y), fmaxf(l0.z, l0.w)),
                     fmaxf(fmaxf(l1.x, l1.y), fmaxf(l1.z, l1.w)));
#pragma unroll
    for (int o = 16; o > 0; o >>= 1)
        mx = fmaxf(mx, __shfl_xor_sync(0xffffffffu, mx, o));

    float se = expf(l0.x - mx) + expf(l0.y - mx) + expf(l0.z - mx) + expf(l0.w - mx)
             + expf(l1.x - mx) + expf(l1.y - mx) + expf(l1.z - mx) + expf(l1.w - mx);
    float sl = a0.x + a0.y + a0.z + a0.w + a1.x + a1.y + a1.z + a1.w;
    float sll = a0.x * l0.x + a0.y * l0.y + a0.z * l0.z + a0.w * l0.w
              + a1.x * l1.x + a1.y * l1.y + a1.z * l1.z + a1.w * l1.w;
#pragma unroll
    for (int o = 16; o > 0; o >>= 1) {
        se  += __shfl_xor_sync(0xffffffffu, se, o);
        sl  += __shfl_xor_sync(0xffffffffu, sl, o);
        sll += __shfl_xor_sync(0xffffffffu, sll, o);
    }

    if (lane == 0)
        rowloss[row] = (mx + logf(se)) * sl - sll;
}

// Deterministic final mean over 32768 row losses.
__global__ void final_reduce(const float* __restrict__ rowloss, float* __restrict__ out)
{
    const int v = threadIdx.x;   // 256 threads
    __shared__ float s[256];
    float acc = 0.0f;
    for (int i = v; i < TB; i += 256) acc += rowloss[i];
    s[v] = acc; __syncthreads();
    for (int o = 128; o > 0; o >>= 1) {
        if (v < o) s[v] += s[v + o];
        __syncthreads();
    }
    if (v == 0) out[0] = s[0] * (1.0f / (float)TB);
}

extern "C" void kernel_launch(void* const* d_in, const int* in_sizes, int n_in,
                              void* d_out, int out_size)
{
    const float* inputs  = (const float*)d_in[0];   // (T, B, V)
    const float* labels  = (const float*)d_in[1];   // (T*B, V)
    const float* weights = (const float*)d_in[2];   // (V+N, N)
    const float* bias    = (const float*)d_in[3];   // (N,)
    const float* ow      = (const float*)d_in[4];   // (N, V)
    const float* ob      = (const float*)d_in[5];   // (V,)
    float* out = (float*)d_out;

    float *seq, *part, *logits, *rowloss;
    cudaGetSymbolAddress((void**)&seq, g_seq);
    cudaGetSymbolAddress((void**)&part, g_part);
    cudaGetSymbolAddress((void**)&logits, g_logits);
    cudaGetSymbolAddress((void**)&rowloss, g_rowloss);

    const float* wx = weights;                         // rows [0, V)
    const float* wh = weights + (size_t)V_DIM * N_DIM; // rows [V, V+N)

    // 1) pre[t,b,n] = X @ Wx + bias  (full sequence, one big GEMM)
    mma_gemm<<<dim3(N_DIM / 64, TB / 64, 1), 128>>>(
        inputs, wx, seq, bias, V_DIM, N_DIM, N_DIM, V_DIM);

    // 2) h_0 = tanh(pre_0)
    tanh_slab<<<SLAB / (256 * 4), 256>>>(seq);

    // 3) recurrence: one fused kernel per step (split-K + in-kernel reduce/tanh)
    for (int t = 1; t < T_STEPS; t++) {
        rnn_step<<<dim3(N_DIM / 64, BATCH / 64, NSPLIT), 128>>>(
            seq + (size_t)(t - 1) * SLAB, wh, part, seq + (size_t)t * SLAB);
    }

    // 4) logits = H @ Wo + ob
    mma_gemm<<<dim3(V_DIM / 64, TB / 64, 1), 128>>>(
        seq, ow, logits, ob, N_DIM, V_DIM, V_DIM, N_DIM);

    // 5) per-row loss (warp per row), then deterministic mean
    loss_rows<<<TB / 8, 256>>>(logits, labels, rowloss);
    final_reduce<<<1, 256>>>(rowloss, out);
}